// round 16
// baseline (speedup 1.0000x reference)
#include <cuda_runtime.h>
#include <math_constants.h>

// MoE_27693949124969: B=4, S=4096, D=1024, E=8, top_k=2
// out[t] = sum_k logit_k * ( x[t] @ We[e_k] + be[e_k] ),  e_k = top-2 of (x@Wg+bg)
// R14 core: mma.sync tf32, M128xN128, Kc32, 3 stages, 2x4 warps, 2 CTA/SM,
// persistent work-steal both slots, RED.ADD epilogue, chunk-head ldsm-first.
// R15/R16: plan computed per-CTA (launch removed), gate 64 tok/block, bb-first LDSM.

#define T_TOKENS 16384
#define D_DIM    1024
#define E_EXP    8
#define KT       32          // K chunks of 32 (32*32 = 1024)
#define STAGES   3
#define TS       36          // smem row stride (floats)
#define MTILE    128
#define NTILE    128

// ---------------- device scratch ----------------
__device__ int      g_cnt[2][E_EXP];
__device__ int      g_list[2][E_EXP][T_TOKENS];
__device__ float    g_coef[2][E_EXP][T_TOKENS];
__device__ float    g_Wt[(size_t)E_EXP * D_DIM * D_DIM];   // We^T, RNA tf32-rounded
__device__ unsigned g_wctr;

// ---------------- helpers ----------------
__device__ __forceinline__ float f2tf(float f) {
    unsigned u;
    asm("cvt.rna.tf32.f32 %0, %1;" : "=r"(u) : "f"(f));
    return __uint_as_float(u);
}

__device__ __forceinline__ void mma_tf32(float* d, const unsigned* a,
                                         unsigned b0, unsigned b1) {
    asm volatile(
        "mma.sync.aligned.m16n8k8.row.col.f32.tf32.tf32.f32 "
        "{%0,%1,%2,%3}, {%4,%5,%6,%7}, {%8,%9}, {%0,%1,%2,%3};\n"
        : "+f"(d[0]), "+f"(d[1]), "+f"(d[2]), "+f"(d[3])
        : "r"(a[0]), "r"(a[1]), "r"(a[2]), "r"(a[3]), "r"(b0), "r"(b1));
}

__device__ __forceinline__ void ldsm4(unsigned* r, unsigned addr) {
    asm volatile("ldmatrix.sync.aligned.m8n8.x4.shared.b16 {%0,%1,%2,%3}, [%4];"
                 : "=r"(r[0]), "=r"(r[1]), "=r"(r[2]), "=r"(r[3]) : "r"(addr));
}

__device__ __forceinline__ void cp16(float* s, const float* g) {
    unsigned sa = (unsigned)__cvta_generic_to_shared(s);
    asm volatile("cp.async.cg.shared.global [%0], [%1], 16;\n" :: "r"(sa), "l"(g));
}
#define CP_COMMIT() asm volatile("cp.async.commit_group;\n")
#define CP_WAIT1()  asm volatile("cp.async.wait_group 1;\n")

__device__ __forceinline__ void red_add(float* p, float v) {
    asm volatile("red.global.add.f32 [%0], %1;" :: "l"(p), "f"(v) : "memory");
}

// ---------------- kernel: reset counters + work counter ----------------
__global__ void zero_kernel() {
    int t = threadIdx.x;
    if (t < 2 * E_EXP) ((int*)g_cnt)[t] = 0;
    if (t == 31) g_wctr = 0;
}

// ---------------- kernel: prep = gating (64 tok/block)  ||  We transpose -----------
// blocks [0, 256):    gating, 64 tokens per block (8 per warp)
// blocks [256, 8448): 32x32 tiled transpose of We into g_Wt (RNA tf32)
__global__ __launch_bounds__(256) void prep_kernel(
    const float* __restrict__ x,
    const float* __restrict__ We,   // [E, D, D]
    const float* __restrict__ Wg,   // [D, E]
    const float* __restrict__ bg)   // [E]
{
    __shared__ float ts[32][33];
    __shared__ float sWgT[E_EXP * D_DIM];   // [e][d], 32 KB

    const int tid = threadIdx.x;

    if (blockIdx.x >= 256) {
        // -------- transpose + RNA-round We --------
        int b  = blockIdx.x - 256;           // 8192 blocks = 8 experts x 1024 tiles
        int e  = b >> 10;
        int t  = b & 1023;
        int k0 = (t >> 5) * 32;
        int n0 = (t & 31) * 32;
        int tx = tid & 31;
        int ty = tid >> 5;

        const float* src = We + (size_t)e * D_DIM * D_DIM;
        float*       dst = g_Wt + (size_t)e * D_DIM * D_DIM;

        #pragma unroll
        for (int i = 0; i < 4; i++) {
            int k = k0 + ty + i * 8;
            ts[ty + i * 8][tx] = f2tf(src[(size_t)k * D_DIM + n0 + tx]);
        }
        __syncthreads();
        #pragma unroll
        for (int i = 0; i < 4; i++) {
            int n = n0 + ty + i * 8;
            dst[(size_t)n * D_DIM + k0 + tx] = ts[tx][ty + i * 8];
        }
        return;
    }

    // -------- stage Wg^T into smem (amortized over 64 tokens) --------
    for (int i = tid; i < E_EXP * D_DIM; i += 256) {
        int d = i >> 3, e = i & 7;             // Wg row-major [d][e]
        sWgT[e * D_DIM + d] = Wg[i];
    }
    __syncthreads();

    // -------- gating: 8 tokens per warp --------
    int warp = tid >> 5;
    int lane = tid & 31;
    const float4* wg4 = (const float4*)sWgT;   // [e][256] float4

    for (int ti = 0; ti < 8; ti++) {
        int t = blockIdx.x * 64 + warp * 8 + ti;
        const float4* xr4 = (const float4*)(x + (size_t)t * D_DIM);

        float acc[8] = {0.f,0.f,0.f,0.f,0.f,0.f,0.f,0.f};
        #pragma unroll
        for (int it = 0; it < 8; it++) {
            float4 xv = xr4[it * 32 + lane];
            #pragma unroll
            for (int e = 0; e < 8; e++) {
                float4 w = wg4[e * 256 + it * 32 + lane];
                acc[e] += xv.x * w.x + xv.y * w.y + xv.z * w.z + xv.w * w.w;
            }
        }
        #pragma unroll
        for (int e = 0; e < 8; e++) {
            #pragma unroll
            for (int off = 16; off; off >>= 1)
                acc[e] += __shfl_xor_sync(0xFFFFFFFFu, acc[e], off);
        }

        if (lane == 0) {
            float l[8];
            #pragma unroll
            for (int e = 0; e < 8; e++) l[e] = acc[e] + bg[e];
            int e0 = 0; float v0 = l[0];
            #pragma unroll
            for (int e = 1; e < 8; e++) if (l[e] > v0) { v0 = l[e]; e0 = e; }
            int e1 = -1; float v1 = -CUDART_INF_F;
            #pragma unroll
            for (int e = 0; e < 8; e++)
                if (e != e0 && l[e] > v1) { v1 = l[e]; e1 = e; }

            int p0 = atomicAdd(&g_cnt[0][e0], 1);
            g_list[0][e0][p0] = t;  g_coef[0][e0][p0] = v0;
            int p1 = atomicAdd(&g_cnt[1][e1], 1);
            g_list[1][e1][p1] = t;  g_coef[1][e1][p1] = v1;
        }
    }
}

// ---------------- persistent grouped GEMM, both slots, RED.ADD epilogue ------------
#define TILE_FLOATS (128 * TS)                  // 4608 floats per 128x32 tile
#define STG_FLOATS  (2 * TILE_FLOATS)
#define SMEM_FLOATS (STAGES * STG_FLOATS)       // 27648 floats = 110592 B
#define STG_BYTES   (STG_FLOATS * 4)
#define BOFF_BYTES  (TILE_FLOATS * 4)

__global__ __launch_bounds__(256, 2) void moe_gemm_kernel(
    const float* __restrict__ x,    // raw f32 A (tf32 truncation in mma)
    const float* __restrict__ be,   // [E, D]
    float* __restrict__ out)        // pre-zeroed
{
    extern __shared__ float smem[];

    __shared__ int   s_mcum[2][E_EXP];
    __shared__ int   s_u[2];        // u0, utot
    __shared__ int   s_w;
    __shared__ int   s_tok[128];
    __shared__ float s_cf[128];
    __shared__ float s_be[128];

    const int tid = threadIdx.x;

    // ---- per-CTA plan: prefix sums over g_cnt (replaces plan_kernel) ----
    if (tid == 0) {
        int u[2];
        #pragma unroll
        for (int s = 0; s < 2; s++) {
            int c = 0;
            #pragma unroll
            for (int e = 0; e < E_EXP; e++) {
                c += (g_cnt[s][e] + MTILE - 1) / MTILE;
                s_mcum[s][e] = c;
            }
            u[s] = c * (D_DIM / NTILE);
        }
        s_u[0] = u[0];
        s_u[1] = u[0] + u[1];
    }
    __syncthreads();
    const int u0   = s_u[0];
    const int utot = s_u[1];

    const int lane = tid & 31, warp = tid >> 5;
    const int wm = warp >> 2, wn = warp & 3;    // 2x4 warp grid, 64x32 warp tile
    const int qr = lane >> 2, qc = lane & 3;
    const int g  = lane >> 3, r  = lane & 7;

    const unsigned smem_u = (unsigned)__cvta_generic_to_shared(smem);
    const unsigned a_lds = ((wm * 64 + (g & 1) * 8 + r) * TS + (g >> 1) * 4) * 4;
    const unsigned b_lds = ((wn * 32 + (g >> 1) * 8 + r) * TS + (g & 1) * 4) * 4;

    // fixed per-thread copy slots: 1024 float4 per tile plane, 4 per thread
    int cp_row[4], cp_c4[4];
    #pragma unroll
    for (int i = 0; i < 4; i++) {
        int u = tid + i * 256;
        cp_row[i] = u >> 3;
        cp_c4[i]  = u & 7;
    }

    for (;;) {
        if (tid == 0) s_w = (int)atomicAdd(&g_wctr, 1u);
        __syncthreads();                     // epilogue done; s_w visible
        const int w = s_w;
        if (w >= utot) break;

        const int slot = (w >= u0) ? 1 : 0;
        const int wl   = w - (slot ? u0 : 0);
        const int mtg  = wl >> 3;            // global M-tile within slot
        const int nt   = wl & 7;             // N tile
        int e = 0, base = 0;
        #pragma unroll
        for (int i = 0; i < E_EXP; i++) {
            int c = s_mcum[slot][i];
            if (mtg >= c) { e = i + 1; base = c; }
        }
        const int mt    = mtg - base;
        const int nrows = g_cnt[slot][e];
        const int row0  = mt * MTILE;
        const int mrows = min(MTILE, nrows - row0);

        if (tid < 128) {
            int tok = 0; float cf = 0.f;
            if (tid < mrows) {
                tok = g_list[slot][e][row0 + tid];
                cf  = g_coef[slot][e][row0 + tid];
            }
            s_tok[tid] = tok;
            s_cf[tid]  = cf;
            s_be[tid]  = be[e * D_DIM + nt * NTILE + tid];
        }
        __syncthreads();

        const float* a_g[4];
        const float* b_g[4];
        int soff[4];
        const float* Wb = g_Wt + ((size_t)e * D_DIM + nt * NTILE) * D_DIM;
        #pragma unroll
        for (int i = 0; i < 4; i++) {
            a_g[i]  = x  + (size_t)s_tok[cp_row[i]] * D_DIM + cp_c4[i] * 4;
            b_g[i]  = Wb + (size_t)cp_row[i]        * D_DIM + cp_c4[i] * 4;
            soff[i] = cp_row[i] * TS + cp_c4[i] * 4;
        }

        // prologue: prefetch stages 0,1
        #pragma unroll
        for (int s = 0; s < 2; s++) {
            float* Ast = smem + s * STG_FLOATS;
            float* Bst = Ast + TILE_FLOATS;
            #pragma unroll
            for (int i = 0; i < 4; i++) cp16(Ast + soff[i], a_g[i] + s * 32);
            #pragma unroll
            for (int i = 0; i < 4; i++) cp16(Bst + soff[i], b_g[i] + s * 32);
            CP_COMMIT();
        }

        float acc[4][4][4];
        #pragma unroll
        for (int i = 0; i < 4; i++)
            #pragma unroll
            for (int j = 0; j < 4; j++)
                #pragma unroll
                for (int c = 0; c < 4; c++) acc[i][j][c] = 0.f;

        for (int kc = 0; kc < KT; kc++) {
            const int st = kc % STAGES;
            CP_WAIT1();            // chunk kc resident
            __syncthreads();       // also guards reuse of stage (kc+2)%STAGES

            const unsigned sA = smem_u + st * STG_BYTES + a_lds;
            const unsigned sB = smem_u + st * STG_BYTES + BOFF_BYTES + b_lds;

            // ---- ks=0 fragments FIRST (B before A): tensor pipe starts asap ----
            unsigned a0[4][4], bb0[2][4];
            #pragma unroll
            for (int fnp = 0; fnp < 2; fnp++)
                ldsm4(bb0[fnp], sB + fnp * (16 * TS * 4));
            #pragma unroll
            for (int fm = 0; fm < 4; fm++)
                ldsm4(a0[fm], sA + fm * (16 * TS * 4));

            // ---- stage refill overlaps the MMA work below ----
            if (kc + 2 < KT) {
                const int sn = (kc + 2) % STAGES;
                float* Ast = smem + sn * STG_FLOATS;
                float* Bst = Ast + TILE_FLOATS;
                #pragma unroll
                for (int i = 0; i < 4; i++) cp16(Ast + soff[i], a_g[i] + (kc + 2) * 32);
                #pragma unroll
                for (int i = 0; i < 4; i++) cp16(Bst + soff[i], b_g[i] + (kc + 2) * 32);
            }
            CP_COMMIT();           // one group per iteration (possibly empty)

            #pragma unroll
            for (int fm = 0; fm < 4; fm++)
                #pragma unroll
                for (int fn = 0; fn < 4; fn++)
                    mma_tf32(acc[fm][fn], a0[fm],
                             bb0[fn >> 1][(fn & 1) * 2], bb0[fn >> 1][(fn & 1) * 2 + 1]);

            #pragma unroll
            for (int ks = 1; ks < 4; ks++) {
                unsigned a[4][4], bb[2][4];
                #pragma unroll
                for (int fnp = 0; fnp < 2; fnp++)
                    ldsm4(bb[fnp], sB + fnp * (16 * TS * 4) + ks * 32);
                #pragma unroll
                for (int fm = 0; fm < 4; fm++)
                    ldsm4(a[fm], sA + fm * (16 * TS * 4) + ks * 32);
                #pragma unroll
                for (int fm = 0; fm < 4; fm++)
                    #pragma unroll
                    for (int fn = 0; fn < 4; fn++)
                        mma_tf32(acc[fm][fn], a[fm],
                                 bb[fn >> 1][(fn & 1) * 2], bb[fn >> 1][(fn & 1) * 2 + 1]);
            }
        }

        // ---- epilogue: RED.ADD into pre-zeroed out ----
        #pragma unroll
        for (int fm = 0; fm < 4; fm++) {
            int rb = wm * 64 + fm * 16 + qr;
            #pragma unroll
            for (int fn = 0; fn < 4; fn++) {
                int lc = wn * 32 + fn * 8 + qc * 2;
                float be0 = s_be[lc], be1 = s_be[lc + 1];
                #pragma unroll
                for (int h = 0; h < 2; h++) {
                    int rr = rb + h * 8;
                    if (rr < mrows) {
                        int   tok = s_tok[rr];
                        float cf  = s_cf[rr];
                        float* po = out + (size_t)tok * D_DIM + nt * NTILE + lc;
                        red_add(po,     cf * (acc[fm][fn][h * 2 + 0] + be0));
                        red_add(po + 1, cf * (acc[fm][fn][h * 2 + 1] + be1));
                    }
                }
            }
        }
    }
}

// ---------------- launch ----------------
extern "C" void kernel_launch(void* const* d_in, const int* in_sizes, int n_in,
                              void* d_out, int out_size)
{
    const float* x  = (const float*)d_in[0];
    // d_in[1] = router_mask (unused)
    const float* We = (const float*)d_in[2];
    const float* be = (const float*)d_in[3];
    const float* Wg = (const float*)d_in[4];
    const float* bg = (const float*)d_in[5];
    float* out = (float*)d_out;

    const int smem_bytes = SMEM_FLOATS * sizeof(float);   // 110,592 B
    cudaFuncSetAttribute(moe_gemm_kernel,
                         cudaFuncAttributeMaxDynamicSharedMemorySize, smem_bytes);

    cudaMemsetAsync(out, 0, (size_t)out_size * sizeof(float), 0);
    zero_kernel<<<1, 32>>>();
    prep_kernel<<<256 + 8192, 256>>>(x, We, Wg, bg);

    moe_gemm_kernel<<<296, 256, smem_bytes>>>(x, be, out);   // both slots, one launch
}

// round 17
// speedup vs baseline: 1.1357x; 1.1357x over previous
#include <cuda_runtime.h>
#include <math_constants.h>

// MoE_27693949124969: B=4, S=4096, D=1024, E=8, top_k=2
// out[t] = sum_k logit_k * ( x[t] @ We[e_k] + be[e_k] ),  e_k = top-2 of (x@Wg+bg)
// R14 core (461.9us): mma.sync tf32, M128xN128, Kc32, 3 stages, 2x4 warps,
// 2 CTA/SM, persistent work-steal both slots, RED.ADD epilogue, chunk-head
// ldsm-first. R17: ONLY change vs R14 = plan computed per-CTA (plan_kernel
// launch removed; g_wctr reset in zero_kernel). Gate back to warp-per-token.

#define T_TOKENS 16384
#define D_DIM    1024
#define E_EXP    8
#define KT       32          // K chunks of 32 (32*32 = 1024)
#define STAGES   3
#define TS       36          // smem row stride (floats)
#define MTILE    128
#define NTILE    128

// ---------------- device scratch ----------------
__device__ int      g_cnt[2][E_EXP];
__device__ int      g_list[2][E_EXP][T_TOKENS];
__device__ float    g_coef[2][E_EXP][T_TOKENS];
__device__ float    g_Wt[(size_t)E_EXP * D_DIM * D_DIM];   // We^T, RNA tf32-rounded
__device__ unsigned g_wctr;

// ---------------- helpers ----------------
__device__ __forceinline__ float f2tf(float f) {
    unsigned u;
    asm("cvt.rna.tf32.f32 %0, %1;" : "=r"(u) : "f"(f));
    return __uint_as_float(u);
}

__device__ __forceinline__ void mma_tf32(float* d, const unsigned* a,
                                         unsigned b0, unsigned b1) {
    asm volatile(
        "mma.sync.aligned.m16n8k8.row.col.f32.tf32.tf32.f32 "
        "{%0,%1,%2,%3}, {%4,%5,%6,%7}, {%8,%9}, {%0,%1,%2,%3};\n"
        : "+f"(d[0]), "+f"(d[1]), "+f"(d[2]), "+f"(d[3])
        : "r"(a[0]), "r"(a[1]), "r"(a[2]), "r"(a[3]), "r"(b0), "r"(b1));
}

__device__ __forceinline__ void ldsm4(unsigned* r, unsigned addr) {
    asm volatile("ldmatrix.sync.aligned.m8n8.x4.shared.b16 {%0,%1,%2,%3}, [%4];"
                 : "=r"(r[0]), "=r"(r[1]), "=r"(r[2]), "=r"(r[3]) : "r"(addr));
}

__device__ __forceinline__ void cp16(float* s, const float* g) {
    unsigned sa = (unsigned)__cvta_generic_to_shared(s);
    asm volatile("cp.async.cg.shared.global [%0], [%1], 16;\n" :: "r"(sa), "l"(g));
}
#define CP_COMMIT() asm volatile("cp.async.commit_group;\n")
#define CP_WAIT1()  asm volatile("cp.async.wait_group 1;\n")

__device__ __forceinline__ void red_add(float* p, float v) {
    asm volatile("red.global.add.f32 [%0], %1;" :: "l"(p), "f"(v) : "memory");
}

// ---------------- kernel: reset counters + work counter ----------------
__global__ void zero_kernel() {
    int t = threadIdx.x;
    if (t < 2 * E_EXP) ((int*)g_cnt)[t] = 0;
    if (t == 31) g_wctr = 0;
}

// ---------------- kernel: prep = gating (smem Wg)  ||  We transpose ----------------
// blocks [0, 2048):     gating, 8 tokens per block (warp-per-token)
// blocks [2048, 10240): 32x32 tiled transpose of We into g_Wt (RNA tf32)
__global__ __launch_bounds__(256) void prep_kernel(
    const float* __restrict__ x,
    const float* __restrict__ We,   // [E, D, D]
    const float* __restrict__ Wg,   // [D, E]
    const float* __restrict__ bg)   // [E]
{
    __shared__ float ts[32][33];
    __shared__ float sWgT[E_EXP * D_DIM];   // [e][d], 32 KB

    const int tid = threadIdx.x;

    if (blockIdx.x >= 2048) {
        // -------- transpose + RNA-round We --------
        int b  = blockIdx.x - 2048;          // 8192 blocks = 8 experts x 1024 tiles
        int e  = b >> 10;
        int t  = b & 1023;
        int k0 = (t >> 5) * 32;
        int n0 = (t & 31) * 32;
        int tx = tid & 31;
        int ty = tid >> 5;

        const float* src = We + (size_t)e * D_DIM * D_DIM;
        float*       dst = g_Wt + (size_t)e * D_DIM * D_DIM;

        #pragma unroll
        for (int i = 0; i < 4; i++) {
            int k = k0 + ty + i * 8;
            ts[ty + i * 8][tx] = f2tf(src[(size_t)k * D_DIM + n0 + tx]);
        }
        __syncthreads();
        #pragma unroll
        for (int i = 0; i < 4; i++) {
            int n = n0 + ty + i * 8;
            dst[(size_t)n * D_DIM + k0 + tx] = ts[tx][ty + i * 8];
        }
        return;
    }

    // -------- stage Wg^T into smem --------
    for (int i = tid; i < E_EXP * D_DIM; i += 256) {
        int d = i >> 3, e = i & 7;             // Wg row-major [d][e]
        sWgT[e * D_DIM + d] = Wg[i];
    }
    __syncthreads();

    // -------- gating: warp per token --------
    int warp = tid >> 5;
    int lane = tid & 31;
    int t = blockIdx.x * 8 + warp;

    const float4* xr4 = (const float4*)(x + (size_t)t * D_DIM);
    const float4* wg4 = (const float4*)sWgT;   // [e][256] float4

    float acc[8] = {0.f,0.f,0.f,0.f,0.f,0.f,0.f,0.f};
    #pragma unroll
    for (int it = 0; it < 8; it++) {
        float4 xv = xr4[it * 32 + lane];
        #pragma unroll
        for (int e = 0; e < 8; e++) {
            float4 w = wg4[e * 256 + it * 32 + lane];
            acc[e] += xv.x * w.x + xv.y * w.y + xv.z * w.z + xv.w * w.w;
        }
    }
    #pragma unroll
    for (int e = 0; e < 8; e++) {
        #pragma unroll
        for (int off = 16; off; off >>= 1)
            acc[e] += __shfl_xor_sync(0xFFFFFFFFu, acc[e], off);
    }

    if (lane == 0) {
        float l[8];
        #pragma unroll
        for (int e = 0; e < 8; e++) l[e] = acc[e] + bg[e];
        int e0 = 0; float v0 = l[0];
        #pragma unroll
        for (int e = 1; e < 8; e++) if (l[e] > v0) { v0 = l[e]; e0 = e; }
        int e1 = -1; float v1 = -CUDART_INF_F;
        #pragma unroll
        for (int e = 0; e < 8; e++)
            if (e != e0 && l[e] > v1) { v1 = l[e]; e1 = e; }

        int p0 = atomicAdd(&g_cnt[0][e0], 1);
        g_list[0][e0][p0] = t;  g_coef[0][e0][p0] = v0;
        int p1 = atomicAdd(&g_cnt[1][e1], 1);
        g_list[1][e1][p1] = t;  g_coef[1][e1][p1] = v1;
    }
}

// ---------------- persistent grouped GEMM, both slots, RED.ADD epilogue ------------
#define TILE_FLOATS (128 * TS)                  // 4608 floats per 128x32 tile
#define STG_FLOATS  (2 * TILE_FLOATS)
#define SMEM_FLOATS (STAGES * STG_FLOATS)       // 27648 floats = 110592 B
#define STG_BYTES   (STG_FLOATS * 4)
#define BOFF_BYTES  (TILE_FLOATS * 4)

__global__ __launch_bounds__(256, 2) void moe_gemm_kernel(
    const float* __restrict__ x,    // raw f32 A (tf32 truncation in mma)
    const float* __restrict__ be,   // [E, D]
    float* __restrict__ out)        // pre-zeroed
{
    extern __shared__ float smem[];

    __shared__ int   s_mcum[2][E_EXP];
    __shared__ int   s_u[2];        // u0, utot
    __shared__ int   s_w;
    __shared__ int   s_tok[128];
    __shared__ float s_cf[128];
    __shared__ float s_be[128];

    const int tid = threadIdx.x;

    // ---- per-CTA plan: prefix sums over g_cnt (replaces plan_kernel) ----
    if (tid == 0) {
        int u[2];
        #pragma unroll
        for (int s = 0; s < 2; s++) {
            int c = 0;
            #pragma unroll
            for (int e = 0; e < E_EXP; e++) {
                c += (g_cnt[s][e] + MTILE - 1) / MTILE;
                s_mcum[s][e] = c;
            }
            u[s] = c * (D_DIM / NTILE);
        }
        s_u[0] = u[0];
        s_u[1] = u[0] + u[1];
    }
    __syncthreads();
    const int u0   = s_u[0];
    const int utot = s_u[1];

    const int lane = tid & 31, warp = tid >> 5;
    const int wm = warp >> 2, wn = warp & 3;    // 2x4 warp grid, 64x32 warp tile
    const int qr = lane >> 2, qc = lane & 3;
    const int g  = lane >> 3, r  = lane & 7;

    const unsigned smem_u = (unsigned)__cvta_generic_to_shared(smem);
    const unsigned a_lds = ((wm * 64 + (g & 1) * 8 + r) * TS + (g >> 1) * 4) * 4;
    const unsigned b_lds = ((wn * 32 + (g >> 1) * 8 + r) * TS + (g & 1) * 4) * 4;

    // fixed per-thread copy slots: 1024 float4 per tile plane, 4 per thread
    int cp_row[4], cp_c4[4];
    #pragma unroll
    for (int i = 0; i < 4; i++) {
        int u = tid + i * 256;
        cp_row[i] = u >> 3;
        cp_c4[i]  = u & 7;
    }

    for (;;) {
        if (tid == 0) s_w = (int)atomicAdd(&g_wctr, 1u);
        __syncthreads();                     // epilogue done; s_w visible
        const int w = s_w;
        if (w >= utot) break;

        const int slot = (w >= u0) ? 1 : 0;
        const int wl   = w - (slot ? u0 : 0);
        const int mtg  = wl >> 3;            // global M-tile within slot
        const int nt   = wl & 7;             // N tile
        int e = 0, base = 0;
        #pragma unroll
        for (int i = 0; i < E_EXP; i++) {
            int c = s_mcum[slot][i];
            if (mtg >= c) { e = i + 1; base = c; }
        }
        const int mt    = mtg - base;
        const int nrows = g_cnt[slot][e];
        const int row0  = mt * MTILE;
        const int mrows = min(MTILE, nrows - row0);

        if (tid < 128) {
            int tok = 0; float cf = 0.f;
            if (tid < mrows) {
                tok = g_list[slot][e][row0 + tid];
                cf  = g_coef[slot][e][row0 + tid];
            }
            s_tok[tid] = tok;
            s_cf[tid]  = cf;
            s_be[tid]  = be[e * D_DIM + nt * NTILE + tid];
        }
        __syncthreads();

        const float* a_g[4];
        const float* b_g[4];
        int soff[4];
        const float* Wb = g_Wt + ((size_t)e * D_DIM + nt * NTILE) * D_DIM;
        #pragma unroll
        for (int i = 0; i < 4; i++) {
            a_g[i]  = x  + (size_t)s_tok[cp_row[i]] * D_DIM + cp_c4[i] * 4;
            b_g[i]  = Wb + (size_t)cp_row[i]        * D_DIM + cp_c4[i] * 4;
            soff[i] = cp_row[i] * TS + cp_c4[i] * 4;
        }

        // prologue: prefetch stages 0,1
        #pragma unroll
        for (int s = 0; s < 2; s++) {
            float* Ast = smem + s * STG_FLOATS;
            float* Bst = Ast + TILE_FLOATS;
            #pragma unroll
            for (int i = 0; i < 4; i++) cp16(Ast + soff[i], a_g[i] + s * 32);
            #pragma unroll
            for (int i = 0; i < 4; i++) cp16(Bst + soff[i], b_g[i] + s * 32);
            CP_COMMIT();
        }

        float acc[4][4][4];
        #pragma unroll
        for (int i = 0; i < 4; i++)
            #pragma unroll
            for (int j = 0; j < 4; j++)
                #pragma unroll
                for (int c = 0; c < 4; c++) acc[i][j][c] = 0.f;

        for (int kc = 0; kc < KT; kc++) {
            const int st = kc % STAGES;
            CP_WAIT1();            // chunk kc resident
            __syncthreads();       // also guards reuse of stage (kc+2)%STAGES

            const unsigned sA = smem_u + st * STG_BYTES + a_lds;
            const unsigned sB = smem_u + st * STG_BYTES + BOFF_BYTES + b_lds;

            // ---- ks=0 fragments FIRST: tensor pipe starts immediately ----
            unsigned a0[4][4], bb0[2][4];
            #pragma unroll
            for (int fm = 0; fm < 4; fm++)
                ldsm4(a0[fm], sA + fm * (16 * TS * 4));
            #pragma unroll
            for (int fnp = 0; fnp < 2; fnp++)
                ldsm4(bb0[fnp], sB + fnp * (16 * TS * 4));

            // ---- stage refill overlaps the MMA work below ----
            if (kc + 2 < KT) {
                const int sn = (kc + 2) % STAGES;
                float* Ast = smem + sn * STG_FLOATS;
                float* Bst = Ast + TILE_FLOATS;
                #pragma unroll
                for (int i = 0; i < 4; i++) cp16(Ast + soff[i], a_g[i] + (kc + 2) * 32);
                #pragma unroll
                for (int i = 0; i < 4; i++) cp16(Bst + soff[i], b_g[i] + (kc + 2) * 32);
            }
            CP_COMMIT();           // one group per iteration (possibly empty)

            #pragma unroll
            for (int fm = 0; fm < 4; fm++)
                #pragma unroll
                for (int fn = 0; fn < 4; fn++)
                    mma_tf32(acc[fm][fn], a0[fm],
                             bb0[fn >> 1][(fn & 1) * 2], bb0[fn >> 1][(fn & 1) * 2 + 1]);

            #pragma unroll
            for (int ks = 1; ks < 4; ks++) {
                unsigned a[4][4], bb[2][4];
                #pragma unroll
                for (int fm = 0; fm < 4; fm++)
                    ldsm4(a[fm], sA + fm * (16 * TS * 4) + ks * 32);
                #pragma unroll
                for (int fnp = 0; fnp < 2; fnp++)
                    ldsm4(bb[fnp], sB + fnp * (16 * TS * 4) + ks * 32);
                #pragma unroll
                for (int fm = 0; fm < 4; fm++)
                    #pragma unroll
                    for (int fn = 0; fn < 4; fn++)
                        mma_tf32(acc[fm][fn], a[fm],
                                 bb[fn >> 1][(fn & 1) * 2], bb[fn >> 1][(fn & 1) * 2 + 1]);
            }
        }

        // ---- epilogue: RED.ADD into pre-zeroed out ----
        #pragma unroll
        for (int fm = 0; fm < 4; fm++) {
            int rb = wm * 64 + fm * 16 + qr;
            #pragma unroll
            for (int fn = 0; fn < 4; fn++) {
                int lc = wn * 32 + fn * 8 + qc * 2;
                float be0 = s_be[lc], be1 = s_be[lc + 1];
                #pragma unroll
                for (int h = 0; h < 2; h++) {
                    int rr = rb + h * 8;
                    if (rr < mrows) {
                        int   tok = s_tok[rr];
                        float cf  = s_cf[rr];
                        float* po = out + (size_t)tok * D_DIM + nt * NTILE + lc;
                        red_add(po,     cf * (acc[fm][fn][h * 2 + 0] + be0));
                        red_add(po + 1, cf * (acc[fm][fn][h * 2 + 1] + be1));
                    }
                }
            }
        }
    }
}

// ---------------- launch ----------------
extern "C" void kernel_launch(void* const* d_in, const int* in_sizes, int n_in,
                              void* d_out, int out_size)
{
    const float* x  = (const float*)d_in[0];
    // d_in[1] = router_mask (unused)
    const float* We = (const float*)d_in[2];
    const float* be = (const float*)d_in[3];
    const float* Wg = (const float*)d_in[4];
    const float* bg = (const float*)d_in[5];
    float* out = (float*)d_out;

    const int smem_bytes = SMEM_FLOATS * sizeof(float);   // 110,592 B
    cudaFuncSetAttribute(moe_gemm_kernel,
                         cudaFuncAttributeMaxDynamicSharedMemorySize, smem_bytes);

    cudaMemsetAsync(out, 0, (size_t)out_size * sizeof(float), 0);
    zero_kernel<<<1, 32>>>();
    prep_kernel<<<2048 + 8192, 256>>>(x, We, Wg, bg);

    moe_gemm_kernel<<<296, 256, smem_bytes>>>(x, be, out);   // both slots, one launch
}